// round 1
// baseline (speedup 1.0000x reference)
#include <cuda_runtime.h>
#include <math.h>

// Problem constants
#define NT      8192      // tokens = B*S
#define DD      512       // dim_model
#define FF      2048      // dim_feedforward
#define EE      8         // experts
#define MAXTOK  8192      // per-expert worst case (top-2 distinct => <= NT)

// ---------------- scratch (device globals; no allocations allowed) ----------
__device__ __align__(16) int   g_cnt[EE];
__device__ __align__(16) int   g_tok[EE * MAXTOK];       // token id per (e, slot)
__device__ __align__(16) int   g_pos[NT * 2];            // e*MAXTOK+slot per (token,k)
__device__ __align__(16) float g_wt [NT * 2];            // renormalized gate weights
__device__ __align__(16) float g_hidden[(size_t)EE * MAXTOK * FF];  // 512 MB
__device__ __align__(16) float g_y[(size_t)EE * MAXTOK * DD];       // 128 MB

// ---------------- counters reset (graph replays re-run this) ----------------
__global__ void zero_cnt_kernel() {
    if (threadIdx.x < EE) g_cnt[threadIdx.x] = 0;
}

// ---------------- router: one warp per token --------------------------------
__global__ void router_kernel(const float* __restrict__ x,
                              const float* __restrict__ rw,
                              const float* __restrict__ rb) {
    __shared__ float srw[DD * EE];   // 16 KB router weights
    const int tid = threadIdx.x;
    for (int i = tid; i < DD * EE; i += blockDim.x) srw[i] = rw[i];
    __syncthreads();

    const int warp = tid >> 5;
    const int lane = tid & 31;
    const int t = blockIdx.x * (blockDim.x >> 5) + warp;
    if (t >= NT) return;

    const float* __restrict__ xr = x + (size_t)t * DD;
    float acc[EE];
#pragma unroll
    for (int e = 0; e < EE; e++) acc[e] = 0.f;

    for (int d = lane; d < DD; d += 32) {
        const float xv = xr[d];
#pragma unroll
        for (int e = 0; e < EE; e++) acc[e] = fmaf(xv, srw[d * EE + e], acc[e]);
    }
#pragma unroll
    for (int e = 0; e < EE; e++) {
#pragma unroll
        for (int o = 16; o > 0; o >>= 1)
            acc[e] += __shfl_xor_sync(0xffffffffu, acc[e], o);
    }

    if (lane == 0) {
#pragma unroll
        for (int e = 0; e < EE; e++) acc[e] += rb[e];
        // top-2 logits; ties -> lowest index (matches jax.lax.top_k)
        int e0 = 0;
#pragma unroll
        for (int e = 1; e < EE; e++) if (acc[e] > acc[e0]) e0 = e;
        int e1 = -1;
#pragma unroll
        for (int e = 0; e < EE; e++) {
            if (e == e0) continue;
            if (e1 < 0 || acc[e] > acc[e1]) e1 = e;
        }
        // renormalized top-2 softmax weights: w0 = g0/(g0+g1) = 1/(1+exp(l1-l0))
        const float r = expf(acc[e1] - acc[e0]);
        const float w0 = 1.f / (1.f + r);
        const float w1 = r / (1.f + r);

        const int s0 = atomicAdd(&g_cnt[e0], 1);
        const int s1 = atomicAdd(&g_cnt[e1], 1);
        g_tok[e0 * MAXTOK + s0] = t;
        g_tok[e1 * MAXTOK + s1] = t;
        g_pos[2 * t]     = e0 * MAXTOK + s0;
        g_pos[2 * t + 1] = e1 * MAXTOK + s1;
        g_wt [2 * t]     = w0;
        g_wt [2 * t + 1] = w1;
    }
}

// ---------------- GEMM1: hidden = relu(x[tok] @ w1[e] + b1[e]) ---------------
// C[n_e, FF] tiles of 128x128, BK=16, 256 threads, 8x8 microtile.
__global__ void __launch_bounds__(256, 2)
ffn1_kernel(const float* __restrict__ x,
            const float* __restrict__ w1,
            const float* __restrict__ b1) {
    const int e   = blockIdx.z;
    const int n_e = g_cnt[e];
    const int m0  = blockIdx.y * 128;
    if (m0 >= n_e) return;
    const int n0  = blockIdx.x * 128;

    __shared__ float As[16][128];
    __shared__ float Bs[16][128];

    const int tid = threadIdx.x;
    const int ar  = tid & 127;     // A row within tile
    const int ac  = tid >> 7;      // 0..1 -> which float4 of the k-slab
    int arow_idx = m0 + ar;
    if (arow_idx >= n_e) arow_idx = n_e - 1;   // clamp (store is guarded)
    const int tok = g_tok[e * MAXTOK + arow_idx];
    const float* __restrict__ arow = x + (size_t)tok * DD;
    const float* __restrict__ Bg   = w1 + (size_t)e * DD * FF + n0;

    const int bn = (tid & 31) * 4; // B col within tile
    const int bk = tid >> 5;       // 0..7
    const int tx = (tid & 15) * 8;
    const int ty = (tid >> 4) * 8;

    float acc[8][8];
#pragma unroll
    for (int i = 0; i < 8; i++)
#pragma unroll
        for (int j = 0; j < 8; j++) acc[i][j] = 0.f;

    for (int k0 = 0; k0 < DD; k0 += 16) {
        const float4 av0 = *(const float4*)(arow + k0 + ac * 4);
        const float4 av1 = *(const float4*)(arow + k0 + 8 + ac * 4);
        const float4 bv0 = *(const float4*)(Bg + (size_t)(k0 + bk) * FF + bn);
        const float4 bv1 = *(const float4*)(Bg + (size_t)(k0 + bk + 8) * FF + bn);
        __syncthreads();
        As[ac * 4 + 0][ar] = av0.x; As[ac * 4 + 1][ar] = av0.y;
        As[ac * 4 + 2][ar] = av0.z; As[ac * 4 + 3][ar] = av0.w;
        As[8 + ac * 4 + 0][ar] = av1.x; As[8 + ac * 4 + 1][ar] = av1.y;
        As[8 + ac * 4 + 2][ar] = av1.z; As[8 + ac * 4 + 3][ar] = av1.w;
        *(float4*)&Bs[bk][bn]     = bv0;
        *(float4*)&Bs[bk + 8][bn] = bv1;
        __syncthreads();
#pragma unroll
        for (int k = 0; k < 16; k++) {
            float a[8], b[8];
            *(float4*)(a)     = *(const float4*)&As[k][ty];
            *(float4*)(a + 4) = *(const float4*)&As[k][ty + 4];
            *(float4*)(b)     = *(const float4*)&Bs[k][tx];
            *(float4*)(b + 4) = *(const float4*)&Bs[k][tx + 4];
#pragma unroll
            for (int i = 0; i < 8; i++)
#pragma unroll
                for (int j = 0; j < 8; j++)
                    acc[i][j] = fmaf(a[i], b[j], acc[i][j]);
        }
    }

    float bb[8];
#pragma unroll
    for (int j = 0; j < 8; j++) bb[j] = b1[e * FF + n0 + tx + j];
    float* __restrict__ hbase = g_hidden + (size_t)e * MAXTOK * FF;
#pragma unroll
    for (int i = 0; i < 8; i++) {
        const int m = m0 + ty + i;
        if (m < n_e) {
            float o[8];
#pragma unroll
            for (int j = 0; j < 8; j++) o[j] = fmaxf(acc[i][j] + bb[j], 0.f);
            float* dst = hbase + (size_t)m * FF + n0 + tx;
            *(float4*)dst       = *(float4*)o;
            *(float4*)(dst + 4) = *(float4*)(o + 4);
        }
    }
}

// ---------------- GEMM2: y = hidden @ w2[e] + b2[e] --------------------------
__global__ void __launch_bounds__(256, 2)
ffn2_kernel(const float* __restrict__ w2,
            const float* __restrict__ b2) {
    const int e   = blockIdx.z;
    const int n_e = g_cnt[e];
    const int m0  = blockIdx.y * 128;
    if (m0 >= n_e) return;
    const int n0  = blockIdx.x * 128;

    __shared__ float As[16][128];
    __shared__ float Bs[16][128];

    const int tid = threadIdx.x;
    const int ar  = tid & 127;
    const int ac  = tid >> 7;
    int arow_idx = m0 + ar;
    if (arow_idx >= n_e) arow_idx = n_e - 1;
    const float* __restrict__ arow =
        g_hidden + ((size_t)e * MAXTOK + arow_idx) * FF;
    const float* __restrict__ Bg = w2 + (size_t)e * FF * DD + n0;

    const int bn = (tid & 31) * 4;
    const int bk = tid >> 5;
    const int tx = (tid & 15) * 8;
    const int ty = (tid >> 4) * 8;

    float acc[8][8];
#pragma unroll
    for (int i = 0; i < 8; i++)
#pragma unroll
        for (int j = 0; j < 8; j++) acc[i][j] = 0.f;

    for (int k0 = 0; k0 < FF; k0 += 16) {
        const float4 av0 = *(const float4*)(arow + k0 + ac * 4);
        const float4 av1 = *(const float4*)(arow + k0 + 8 + ac * 4);
        const float4 bv0 = *(const float4*)(Bg + (size_t)(k0 + bk) * DD + bn);
        const float4 bv1 = *(const float4*)(Bg + (size_t)(k0 + bk + 8) * DD + bn);
        __syncthreads();
        As[ac * 4 + 0][ar] = av0.x; As[ac * 4 + 1][ar] = av0.y;
        As[ac * 4 + 2][ar] = av0.z; As[ac * 4 + 3][ar] = av0.w;
        As[8 + ac * 4 + 0][ar] = av1.x; As[8 + ac * 4 + 1][ar] = av1.y;
        As[8 + ac * 4 + 2][ar] = av1.z; As[8 + ac * 4 + 3][ar] = av1.w;
        *(float4*)&Bs[bk][bn]     = bv0;
        *(float4*)&Bs[bk + 8][bn] = bv1;
        __syncthreads();
#pragma unroll
        for (int k = 0; k < 16; k++) {
            float a[8], b[8];
            *(float4*)(a)     = *(const float4*)&As[k][ty];
            *(float4*)(a + 4) = *(const float4*)&As[k][ty + 4];
            *(float4*)(b)     = *(const float4*)&Bs[k][tx];
            *(float4*)(b + 4) = *(const float4*)&Bs[k][tx + 4];
#pragma unroll
            for (int i = 0; i < 8; i++)
#pragma unroll
                for (int j = 0; j < 8; j++)
                    acc[i][j] = fmaf(a[i], b[j], acc[i][j]);
        }
    }

    float bb[8];
#pragma unroll
    for (int j = 0; j < 8; j++) bb[j] = b2[e * DD + n0 + tx + j];
    float* __restrict__ ybase = g_y + (size_t)e * MAXTOK * DD;
#pragma unroll
    for (int i = 0; i < 8; i++) {
        const int m = m0 + ty + i;
        if (m < n_e) {
            float o[8];
#pragma unroll
            for (int j = 0; j < 8; j++) o[j] = acc[i][j] + bb[j];
            float* dst = ybase + (size_t)m * DD + n0 + tx;
            *(float4*)dst       = *(float4*)o;
            *(float4*)(dst + 4) = *(float4*)(o + 4);
        }
    }
}

// ---------------- combine: out[t] = w0*y[pos0] + w1*y[pos1] ------------------
__global__ void combine_kernel(float* __restrict__ out) {
    const int i = blockIdx.x * blockDim.x + threadIdx.x;   // over NT * DD/4
    const int t  = i >> 7;     // DD/4 = 128 float4 per token
    const int d4 = i & 127;
    const float w0  = g_wt[2 * t];
    const float w1v = g_wt[2 * t + 1];
    const int p0 = g_pos[2 * t];
    const int p1 = g_pos[2 * t + 1];
    const float4* __restrict__ y4 = (const float4*)g_y;
    const float4 a = y4[(size_t)p0 * 128 + d4];
    const float4 b = y4[(size_t)p1 * 128 + d4];
    float4 r;
    r.x = w0 * a.x + w1v * b.x;
    r.y = w0 * a.y + w1v * b.y;
    r.z = w0 * a.z + w1v * b.z;
    r.w = w0 * a.w + w1v * b.w;
    ((float4*)out)[i] = r;
}

// ---------------- launch -----------------------------------------------------
extern "C" void kernel_launch(void* const* d_in, const int* in_sizes, int n_in,
                              void* d_out, int out_size) {
    const float* x   = (const float*)d_in[0];   // [2,4096,512]
    const float* rw  = (const float*)d_in[1];   // [512,8]
    const float* rb  = (const float*)d_in[2];   // [8]
    const float* w1  = (const float*)d_in[3];   // [8,512,2048]
    const float* b1  = (const float*)d_in[4];   // [8,2048]
    const float* w2  = (const float*)d_in[5];   // [8,2048,512]
    const float* b2  = (const float*)d_in[6];   // [8,512]
    float* out = (float*)d_out;                 // [2,4096,512]

    zero_cnt_kernel<<<1, 32>>>();
    router_kernel<<<NT / 8, 256>>>(x, rw, rb);
    ffn1_kernel<<<dim3(FF / 128, MAXTOK / 128, EE), 256>>>(x, w1, b1);
    ffn2_kernel<<<dim3(DD / 128, MAXTOK / 128, EE), 256>>>(w2, b2);
    combine_kernel<<<(NT * DD / 4) / 256, 256>>>(out);
}

// round 5
// speedup vs baseline: 1.9392x; 1.9392x over previous
#include <cuda_runtime.h>
#include <cstdint>
#include <math.h>

// Problem constants
#define NT      8192      // tokens = B*S
#define DD      512       // dim_model
#define FF      2048      // dim_feedforward
#define EE      8         // experts
#define MAXTOK  8192      // per-expert worst case

// ---------------- scratch (device globals; no allocations allowed) ----------
__device__ __align__(16) int   g_cnt[EE];
__device__ __align__(16) int   g_pos[NT * 2];            // e*MAXTOK+slot per (token,k)
__device__ __align__(16) float g_wt [NT * 2];            // renormalized gate weights
__device__ __align__(16) float g_xg[(size_t)EE * MAXTOK * DD];      // packed A rows (tf32)
__device__ __align__(16) float g_w1t[(size_t)EE * FF * DD];         // w1^T [E][F][D] (tf32)
__device__ __align__(16) float g_w2t[(size_t)EE * DD * FF];         // w2^T [E][D][F] (tf32)
__device__ __align__(16) float g_hidden[(size_t)EE * MAXTOK * FF];  // hidden (tf32)
__device__ __align__(16) float g_y[(size_t)EE * MAXTOK * DD];       // expert outputs

// ---------------- helpers ----------------------------------------------------
__device__ __forceinline__ uint32_t smem_to_u32(const void* p) {
    uint32_t a;
    asm("{ .reg .u64 t; cvta.to.shared.u64 t, %1; cvt.u32.u64 %0, t; }"
        : "=r"(a) : "l"(p));
    return a;
}
__device__ __forceinline__ float to_tf32(float x) {
    float y;
    asm("cvt.rna.tf32.f32 %0, %1;" : "=f"(y) : "f"(x));
    return y;
}

// ---------------- counters reset --------------------------------------------
__global__ void zero_cnt_kernel() {
    if (threadIdx.x < EE) g_cnt[threadIdx.x] = 0;
}

// ---------------- router: one warp per token --------------------------------
__global__ void router_kernel(const float* __restrict__ x,
                              const float* __restrict__ rw,
                              const float* __restrict__ rb) {
    __shared__ float srw[DD * EE];
    const int tid = threadIdx.x;
    for (int i = tid; i < DD * EE; i += blockDim.x) srw[i] = rw[i];
    __syncthreads();

    const int warp = tid >> 5, lane = tid & 31;
    const int t = blockIdx.x * (blockDim.x >> 5) + warp;
    if (t >= NT) return;

    const float* __restrict__ xr = x + (size_t)t * DD;
    float acc[EE];
#pragma unroll
    for (int e = 0; e < EE; e++) acc[e] = 0.f;
    for (int d = lane; d < DD; d += 32) {
        const float xv = xr[d];
#pragma unroll
        for (int e = 0; e < EE; e++) acc[e] = fmaf(xv, srw[d * EE + e], acc[e]);
    }
#pragma unroll
    for (int e = 0; e < EE; e++)
#pragma unroll
        for (int o = 16; o > 0; o >>= 1)
            acc[e] += __shfl_xor_sync(0xffffffffu, acc[e], o);

    if (lane == 0) {
#pragma unroll
        for (int e = 0; e < EE; e++) acc[e] += rb[e];
        int e0 = 0;
#pragma unroll
        for (int e = 1; e < EE; e++) if (acc[e] > acc[e0]) e0 = e;
        int e1 = -1;
#pragma unroll
        for (int e = 0; e < EE; e++) {
            if (e == e0) continue;
            if (e1 < 0 || acc[e] > acc[e1]) e1 = e;
        }
        const float r = expf(acc[e1] - acc[e0]);
        const float w0 = 1.f / (1.f + r);
        const float w1 = r / (1.f + r);
        const int s0 = atomicAdd(&g_cnt[e0], 1);
        const int s1 = atomicAdd(&g_cnt[e1], 1);
        g_pos[2 * t]     = e0 * MAXTOK + s0;
        g_pos[2 * t + 1] = e1 * MAXTOK + s1;
        g_wt [2 * t]     = w0;
        g_wt [2 * t + 1] = w1;
    }
}

// ---------------- pack: gather token rows, round to tf32 ---------------------
__global__ void pack_kernel(const float* __restrict__ x) {
    const int row = blockIdx.x;            // 0 .. 2*NT-1
    const int t = row >> 1, k = row & 1;
    const int pos = g_pos[2 * t + k];
    const float4* __restrict__ src = (const float4*)(x + (size_t)t * DD);
    float4* __restrict__ dst = (float4*)(g_xg + (size_t)pos * DD);
    float4 v = src[threadIdx.x];
    v.x = to_tf32(v.x); v.y = to_tf32(v.y);
    v.z = to_tf32(v.z); v.w = to_tf32(v.w);
    dst[threadIdx.x] = v;
}

// ---------------- weight transpose (+tf32 round) -----------------------------
// MODE 0: w1 [E][DD][FF] -> g_w1t [E][FF][DD]
// MODE 1: w2 [E][FF][DD] -> g_w2t [E][DD][FF]
template <int MODE>
__global__ void transpose_kernel(const float* __restrict__ in) {
    constexpr int R = (MODE == 0) ? DD : FF;
    constexpr int C = (MODE == 0) ? FF : DD;
    __shared__ float t[32][33];
    const int e = blockIdx.z;
    const float* __restrict__ ip = in + (size_t)e * R * C;
    float* __restrict__ op = ((MODE == 0) ? g_w1t : g_w2t) + (size_t)e * R * C;
    const int c0 = blockIdx.x * 32, r0 = blockIdx.y * 32;
    const int tx = threadIdx.x, ty = threadIdx.y;
#pragma unroll
    for (int i = 0; i < 32; i += 8)
        t[ty + i][tx] = ip[(size_t)(r0 + ty + i) * C + c0 + tx];
    __syncthreads();
#pragma unroll
    for (int i = 0; i < 32; i += 8)
        op[(size_t)(c0 + ty + i) * R + r0 + tx] = to_tf32(t[tx][ty + i]);
}

// ---------------- tf32 mma.sync GEMM -----------------------------------------
// C[e][m][n] = A[e][m][:] . Bt[e][n][:]  (+bias, optional relu+tf32-round)
// CTA 128x128, BK=32, 256 threads = 8 warps (2m x 4n), warp tile 64x32,
// mma.sync.m16n8k8 tf32, double-buffered cp.async.
#define BKF   32
#define PAD   36          // padded smem row stride in floats (16B-aligned, conflict-free)
#define BUFF  (128 * PAD) // floats per (A or B) buffer

template <int MODE>
__global__ void __launch_bounds__(256)
moe_gemm_kernel(const float* __restrict__ bias) {
    constexpr int K    = (MODE == 0) ? DD : FF;
    constexpr int NTOT = (MODE == 0) ? FF : DD;
    const float* __restrict__ A  = (MODE == 0) ? g_xg    : g_hidden;
    const float* __restrict__ Bt = (MODE == 0) ? g_w1t   : g_w2t;
    float* __restrict__ C        = (MODE == 0) ? g_hidden : g_y;

    const int e   = blockIdx.z;
    const int n_e = g_cnt[e];
    const int m0  = blockIdx.y * 128;
    if (m0 >= n_e) return;
    const int n0  = blockIdx.x * 128;

    extern __shared__ float sm[];
    float* As = sm;                  // [2][128*PAD]
    float* Bs = sm + 2 * BUFF;       // [2][128*PAD]

    const int tid  = threadIdx.x;
    const int wid  = tid >> 5, lane = tid & 31;
    const int qid  = lane >> 2, tq = lane & 3;
    const int wm   = (wid >> 2) * 64;     // warp m-base within tile
    const int wn   = (wid & 3) * 32;      // warp n-base within tile

    const float* __restrict__ Ab = A  + ((size_t)e * MAXTOK + m0) * K;
    const float* __restrict__ Bb = Bt + ((size_t)e * NTOT  + n0) * K;

    const int lrow = tid >> 3;   // 0..31, 4 passes of 32 rows
    const int lg   = tid & 7;    // 16B granule within 128B row payload
    const uint32_t sA = smem_to_u32(As);
    const uint32_t sB = smem_to_u32(Bs);

    float acc[4][4][4];
#pragma unroll
    for (int i = 0; i < 4; i++)
#pragma unroll
        for (int j = 0; j < 4; j++)
#pragma unroll
            for (int c = 0; c < 4; c++) acc[i][j][c] = 0.f;

    // ---- tile loader (cp.async, one commit per call)
    auto load_tile = [&](int kt, int buf) {
        const int k0 = kt * BKF;
        const uint32_t ab = sA + (uint32_t)buf * BUFF * 4u;
        const uint32_t bb = sB + (uint32_t)buf * BUFF * 4u;
#pragma unroll
        for (int i = 0; i < 4; i++) {
            const int row = lrow + 32 * i;
            const uint32_t so = (uint32_t)(row * PAD + lg * 4) * 4u;
            asm volatile("cp.async.cg.shared.global [%0], [%1], 16;"
                         :: "r"(ab + so), "l"(Ab + (size_t)row * K + k0 + lg * 4) : "memory");
            asm volatile("cp.async.cg.shared.global [%0], [%1], 16;"
                         :: "r"(bb + so), "l"(Bb + (size_t)row * K + k0 + lg * 4) : "memory");
        }
        asm volatile("cp.async.commit_group;" ::: "memory");
    };

    constexpr int KT = K / BKF;
    load_tile(0, 0);

    for (int kt = 0; kt < KT; kt++) {
        if (kt + 1 < KT) {
            load_tile(kt + 1, (kt + 1) & 1);
            asm volatile("cp.async.wait_group 1;" ::: "memory");
        } else {
            asm volatile("cp.async.wait_group 0;" ::: "memory");
        }
        __syncthreads();

        const float* __restrict__ Asb = As + (kt & 1) * BUFF;
        const float* __restrict__ Bsb = Bs + (kt & 1) * BUFF;

#pragma unroll
        for (int ks = 0; ks < 4; ks++) {
            uint32_t af[4][4], bf[4][2];
            const int c = ks * 8 + tq;
#pragma unroll
            for (int i = 0; i < 4; i++) {
                const int r = wm + i * 16 + qid;
                af[i][0] = __float_as_uint(Asb[r * PAD + c]);
                af[i][1] = __float_as_uint(Asb[(r + 8) * PAD + c]);
                af[i][2] = __float_as_uint(Asb[r * PAD + c + 4]);
                af[i][3] = __float_as_uint(Asb[(r + 8) * PAD + c + 4]);
            }
#pragma unroll
            for (int j = 0; j < 4; j++) {
                const int n = wn + j * 8 + qid;
                bf[j][0] = __float_as_uint(Bsb[n * PAD + c]);
                bf[j][1] = __float_as_uint(Bsb[n * PAD + c + 4]);
            }
#pragma unroll
            for (int i = 0; i < 4; i++)
#pragma unroll
                for (int j = 0; j < 4; j++)
                    asm volatile(
                        "mma.sync.aligned.m16n8k8.row.col.f32.tf32.tf32.f32 "
                        "{%0,%1,%2,%3}, {%4,%5,%6,%7}, {%8,%9}, {%0,%1,%2,%3};"
                        : "+f"(acc[i][j][0]), "+f"(acc[i][j][1]),
                          "+f"(acc[i][j][2]), "+f"(acc[i][j][3])
                        : "r"(af[i][0]), "r"(af[i][1]), "r"(af[i][2]), "r"(af[i][3]),
                          "r"(bf[j][0]), "r"(bf[j][1]));
        }
        __syncthreads();
    }

    // ---- epilogue: bias (+relu +tf32-round for MODE 0), float2 stores
    const float* __restrict__ bb = bias + (size_t)e * NTOT + n0;
    float* __restrict__ Cb = C + ((size_t)e * MAXTOK + m0) * NTOT + n0;

#pragma unroll
    for (int j = 0; j < 4; j++) {
        const int cn = wn + j * 8 + 2 * tq;
        const float b0 = bb[cn], b1 = bb[cn + 1];
#pragma unroll
        for (int i = 0; i < 4; i++) {
            const int r0 = wm + i * 16 + qid;
            const int r1 = r0 + 8;
            float2 v0, v1;
            v0.x = acc[i][j][0] + b0; v0.y = acc[i][j][1] + b1;
            v1.x = acc[i][j][2] + b0; v1.y = acc[i][j][3] + b1;
            if (MODE == 0) {
                v0.x = to_tf32(fmaxf(v0.x, 0.f)); v0.y = to_tf32(fmaxf(v0.y, 0.f));
                v1.x = to_tf32(fmaxf(v1.x, 0.f)); v1.y = to_tf32(fmaxf(v1.y, 0.f));
            }
            if (m0 + r0 < n_e) *(float2*)(Cb + (size_t)r0 * NTOT + cn) = v0;
            if (m0 + r1 < n_e) *(float2*)(Cb + (size_t)r1 * NTOT + cn) = v1;
        }
    }
}

// ---------------- combine: out[t] = w0*y[pos0] + w1*y[pos1] ------------------
__global__ void combine_kernel(float* __restrict__ out) {
    const int i = blockIdx.x * blockDim.x + threadIdx.x;
    const int t  = i >> 7;
    const int d4 = i & 127;
    const float w0  = g_wt[2 * t];
    const float w1v = g_wt[2 * t + 1];
    const int p0 = g_pos[2 * t];
    const int p1 = g_pos[2 * t + 1];
    const float4* __restrict__ y4 = (const float4*)g_y;
    const float4 a = y4[(size_t)p0 * 128 + d4];
    const float4 b = y4[(size_t)p1 * 128 + d4];
    float4 r;
    r.x = w0 * a.x + w1v * b.x;
    r.y = w0 * a.y + w1v * b.y;
    r.z = w0 * a.z + w1v * b.z;
    r.w = w0 * a.w + w1v * b.w;
    ((float4*)out)[i] = r;
}

// ---------------- launch -----------------------------------------------------
#define SMEM_BYTES (4u * BUFF * 4u)   // 2 buffers A + 2 buffers B = 73728 B

extern "C" void kernel_launch(void* const* d_in, const int* in_sizes, int n_in,
                              void* d_out, int out_size) {
    const float* x   = (const float*)d_in[0];
    const float* rw  = (const float*)d_in[1];
    const float* rb  = (const float*)d_in[2];
    const float* w1  = (const float*)d_in[3];
    const float* b1  = (const float*)d_in[4];
    const float* w2  = (const float*)d_in[5];
    const float* b2  = (const float*)d_in[6];
    float* out = (float*)d_out;

    cudaFuncSetAttribute(moe_gemm_kernel<0>,
                         cudaFuncAttributeMaxDynamicSharedMemorySize, SMEM_BYTES);
    cudaFuncSetAttribute(moe_gemm_kernel<1>,
                         cudaFuncAttributeMaxDynamicSharedMemorySize, SMEM_BYTES);

    zero_cnt_kernel<<<1, 32>>>();
    router_kernel<<<NT / 8, 256>>>(x, rw, rb);
    pack_kernel<<<NT * 2, 128>>>(x);

    transpose_kernel<0><<<dim3(FF / 32, DD / 32, EE), dim3(32, 8)>>>(w1);
    transpose_kernel<1><<<dim3(DD / 32, FF / 32, EE), dim3(32, 8)>>>(w2);

    // GEMM1: hidden = relu(xg @ w1t^T + b1)   (K = DD, N = FF)
    moe_gemm_kernel<0><<<dim3(FF / 128, MAXTOK / 128, EE), 256, SMEM_BYTES>>>(b1);
    // GEMM2: y = hidden @ w2t^T + b2          (K = FF, N = DD)
    moe_gemm_kernel<1><<<dim3(DD / 128, MAXTOK / 128, EE), 256, SMEM_BYTES>>>(b2);

    combine_kernel<<<(NT * DD / 4) / 256, 256>>>(out);
}

// round 6
// speedup vs baseline: 3.0841x; 1.5904x over previous
#include <cuda_runtime.h>
#include <cstdint>
#include <math.h>

// Problem constants
#define NT      8192      // tokens = B*S
#define DD      512       // dim_model
#define FF      2048      // dim_feedforward
#define EE      8         // experts
#define MAXTOK  8192      // per-expert worst case

// ---------------- scratch (device globals; no allocations allowed) ----------
__device__ __align__(16) int   g_cnt[EE];
__device__ __align__(16) int   g_pos[NT * 2];            // e*MAXTOK+slot per (token,k)
__device__ __align__(16) float g_wt [NT * 2];            // renormalized gate weights
__device__ __align__(16) float g_xg[(size_t)EE * MAXTOK * DD];      // packed A rows (tf32)
__device__ __align__(16) float g_w1t[(size_t)EE * FF * DD];         // w1^T [E][F][D] (tf32)
__device__ __align__(16) float g_w2t[(size_t)EE * DD * FF];         // w2^T [E][D][F] (tf32)
__device__ __align__(16) float g_hidden[(size_t)EE * MAXTOK * FF];  // hidden (tf32)
__device__ __align__(16) float g_y[(size_t)EE * MAXTOK * DD];       // expert outputs

// ---------------- helpers ----------------------------------------------------
__device__ __forceinline__ uint32_t smem_to_u32(const void* p) {
    uint32_t a;
    asm("{ .reg .u64 t; cvta.to.shared.u64 t, %1; cvt.u32.u64 %0, t; }"
        : "=r"(a) : "l"(p));
    return a;
}
__device__ __forceinline__ float to_tf32(float x) {
    float y;
    asm("cvt.rna.tf32.f32 %0, %1;" : "=f"(y) : "f"(x));
    return y;
}

// ---------------- counters reset --------------------------------------------
__global__ void zero_cnt_kernel() {
    if (threadIdx.x < EE) g_cnt[threadIdx.x] = 0;
}

// ---------------- router: one warp per token --------------------------------
__global__ void router_kernel(const float* __restrict__ x,
                              const float* __restrict__ rw,
                              const float* __restrict__ rb) {
    __shared__ float srw[DD * EE];
    const int tid = threadIdx.x;
    for (int i = tid; i < DD * EE; i += blockDim.x) srw[i] = rw[i];
    __syncthreads();

    const int warp = tid >> 5, lane = tid & 31;
    const int t = blockIdx.x * (blockDim.x >> 5) + warp;
    if (t >= NT) return;

    const float* __restrict__ xr = x + (size_t)t * DD;
    float acc[EE];
#pragma unroll
    for (int e = 0; e < EE; e++) acc[e] = 0.f;
    for (int d = lane; d < DD; d += 32) {
        const float xv = xr[d];
#pragma unroll
        for (int e = 0; e < EE; e++) acc[e] = fmaf(xv, srw[d * EE + e], acc[e]);
    }
#pragma unroll
    for (int e = 0; e < EE; e++)
#pragma unroll
        for (int o = 16; o > 0; o >>= 1)
            acc[e] += __shfl_xor_sync(0xffffffffu, acc[e], o);

    if (lane == 0) {
#pragma unroll
        for (int e = 0; e < EE; e++) acc[e] += rb[e];
        int e0 = 0;
#pragma unroll
        for (int e = 1; e < EE; e++) if (acc[e] > acc[e0]) e0 = e;
        int e1 = -1;
#pragma unroll
        for (int e = 0; e < EE; e++) {
            if (e == e0) continue;
            if (e1 < 0 || acc[e] > acc[e1]) e1 = e;
        }
        const float r = expf(acc[e1] - acc[e0]);
        const float w0 = 1.f / (1.f + r);
        const float w1 = r / (1.f + r);
        const int s0 = atomicAdd(&g_cnt[e0], 1);
        const int s1 = atomicAdd(&g_cnt[e1], 1);
        g_pos[2 * t]     = e0 * MAXTOK + s0;
        g_pos[2 * t + 1] = e1 * MAXTOK + s1;
        g_wt [2 * t]     = w0;
        g_wt [2 * t + 1] = w1;
    }
}

// ---------------- pack: gather token rows, round to tf32 ---------------------
__global__ void pack_kernel(const float* __restrict__ x) {
    const int row = blockIdx.x;            // 0 .. 2*NT-1
    const int t = row >> 1, k = row & 1;
    const int pos = g_pos[2 * t + k];
    const float4* __restrict__ src = (const float4*)(x + (size_t)t * DD);
    float4* __restrict__ dst = (float4*)(g_xg + (size_t)pos * DD);
    float4 v = src[threadIdx.x];
    v.x = to_tf32(v.x); v.y = to_tf32(v.y);
    v.z = to_tf32(v.z); v.w = to_tf32(v.w);
    dst[threadIdx.x] = v;
}

// ---------------- weight transpose (+tf32 round) -----------------------------
// MODE 0: w1 [E][DD][FF] -> g_w1t [E][FF][DD]
// MODE 1: w2 [E][FF][DD] -> g_w2t [E][DD][FF]
template <int MODE>
__global__ void transpose_kernel(const float* __restrict__ in) {
    constexpr int R = (MODE == 0) ? DD : FF;
    constexpr int C = (MODE == 0) ? FF : DD;
    __shared__ float t[32][33];
    const int e = blockIdx.z;
    const float* __restrict__ ip = in + (size_t)e * R * C;
    float* __restrict__ op = ((MODE == 0) ? g_w1t : g_w2t) + (size_t)e * R * C;
    const int c0 = blockIdx.x * 32, r0 = blockIdx.y * 32;
    const int tx = threadIdx.x, ty = threadIdx.y;
#pragma unroll
    for (int i = 0; i < 32; i += 8)
        t[ty + i][tx] = ip[(size_t)(r0 + ty + i) * C + c0 + tx];
    __syncthreads();
#pragma unroll
    for (int i = 0; i < 32; i += 8)
        op[(size_t)(c0 + ty + i) * R + r0 + tx] = to_tf32(t[tx][ty + i]);
}

// ---------------- tf32 mma.sync GEMM -----------------------------------------
// C[e][m][n] = A[e][m][:] . Bt[e][n][:]  (+bias, optional relu+tf32-round)
// CTA 128x128, BK=32, 256 threads = 8 warps (2m x 4n), warp tile 64x32,
// mma.sync.m16n8k8 tf32, double-buffered cp.async, 2 CTAs/SM.
#define BKF   32
#define PAD   36          // padded smem row stride in floats (16B-aligned, conflict-free)
#define BUFF  (128 * PAD) // floats per (A or B) buffer

template <int MODE>
__global__ void __launch_bounds__(256, 2)
moe_gemm_kernel(const float* __restrict__ bias) {
    constexpr int K    = (MODE == 0) ? DD : FF;
    constexpr int NTOT = (MODE == 0) ? FF : DD;
    const float* __restrict__ A  = (MODE == 0) ? g_xg    : g_hidden;
    const float* __restrict__ Bt = (MODE == 0) ? g_w1t   : g_w2t;
    float* __restrict__ C        = (MODE == 0) ? g_hidden : g_y;

    const int e   = blockIdx.z;
    const int n_e = g_cnt[e];
    const int m0  = blockIdx.y * 128;
    if (m0 >= n_e) return;
    const int n0  = blockIdx.x * 128;

    extern __shared__ float sm[];
    float* As = sm;                  // [2][128*PAD]
    float* Bs = sm + 2 * BUFF;       // [2][128*PAD]

    const int tid  = threadIdx.x;
    const int wid  = tid >> 5, lane = tid & 31;
    const int qid  = lane >> 2, tq = lane & 3;
    const int wm   = (wid >> 2) * 64;     // warp m-base within tile
    const int wn   = (wid & 3) * 32;      // warp n-base within tile

    const float* __restrict__ Ab = A  + ((size_t)e * MAXTOK + m0) * K;
    const float* __restrict__ Bb = Bt + ((size_t)e * NTOT  + n0) * K;

    const int lrow = tid >> 3;   // 0..31, 4 passes of 32 rows
    const int lg   = tid & 7;    // 16B granule within 128B row payload
    const uint32_t sA = smem_to_u32(As);
    const uint32_t sB = smem_to_u32(Bs);

    float acc[4][4][4];
#pragma unroll
    for (int i = 0; i < 4; i++)
#pragma unroll
        for (int j = 0; j < 4; j++)
#pragma unroll
            for (int c = 0; c < 4; c++) acc[i][j][c] = 0.f;

    // ---- tile loader (cp.async, one commit per call)
    auto load_tile = [&](int kt, int buf) {
        const int k0 = kt * BKF;
        const uint32_t ab = sA + (uint32_t)buf * BUFF * 4u;
        const uint32_t bb = sB + (uint32_t)buf * BUFF * 4u;
#pragma unroll
        for (int i = 0; i < 4; i++) {
            const int row = lrow + 32 * i;
            const uint32_t so = (uint32_t)(row * PAD + lg * 4) * 4u;
            asm volatile("cp.async.cg.shared.global [%0], [%1], 16;"
                         :: "r"(ab + so), "l"(Ab + (size_t)row * K + k0 + lg * 4) : "memory");
            asm volatile("cp.async.cg.shared.global [%0], [%1], 16;"
                         :: "r"(bb + so), "l"(Bb + (size_t)row * K + k0 + lg * 4) : "memory");
        }
        asm volatile("cp.async.commit_group;" ::: "memory");
    };

    constexpr int KT = K / BKF;
    load_tile(0, 0);

    for (int kt = 0; kt < KT; kt++) {
        if (kt + 1 < KT) {
            load_tile(kt + 1, (kt + 1) & 1);
            asm volatile("cp.async.wait_group 1;" ::: "memory");
        } else {
            asm volatile("cp.async.wait_group 0;" ::: "memory");
        }
        __syncthreads();

        const float* __restrict__ Asb = As + (kt & 1) * BUFF;
        const float* __restrict__ Bsb = Bs + (kt & 1) * BUFF;

#pragma unroll
        for (int ks = 0; ks < 4; ks++) {
            uint32_t af[4][4], bf[4][2];
            const int c = ks * 8 + tq;
#pragma unroll
            for (int i = 0; i < 4; i++) {
                const int r = wm + i * 16 + qid;
                af[i][0] = __float_as_uint(Asb[r * PAD + c]);
                af[i][1] = __float_as_uint(Asb[(r + 8) * PAD + c]);
                af[i][2] = __float_as_uint(Asb[r * PAD + c + 4]);
                af[i][3] = __float_as_uint(Asb[(r + 8) * PAD + c + 4]);
            }
#pragma unroll
            for (int j = 0; j < 4; j++) {
                const int n = wn + j * 8 + qid;
                bf[j][0] = __float_as_uint(Bsb[n * PAD + c]);
                bf[j][1] = __float_as_uint(Bsb[n * PAD + c + 4]);
            }
#pragma unroll
            for (int i = 0; i < 4; i++)
#pragma unroll
                for (int j = 0; j < 4; j++)
                    asm volatile(
                        "mma.sync.aligned.m16n8k8.row.col.f32.tf32.tf32.f32 "
                        "{%0,%1,%2,%3}, {%4,%5,%6,%7}, {%8,%9}, {%0,%1,%2,%3};"
                        : "+f"(acc[i][j][0]), "+f"(acc[i][j][1]),
                          "+f"(acc[i][j][2]), "+f"(acc[i][j][3])
                        : "r"(af[i][0]), "r"(af[i][1]), "r"(af[i][2]), "r"(af[i][3]),
                          "r"(bf[j][0]), "r"(bf[j][1]));
        }
        __syncthreads();
    }

    // ---- epilogue: bias (+relu +tf32-round for MODE 0), float2 stores
    const float* __restrict__ bb = bias + (size_t)e * NTOT + n0;
    float* __restrict__ Cb = C + ((size_t)e * MAXTOK + m0) * NTOT + n0;

#pragma unroll
    for (int j = 0; j < 4; j++) {
        const int cn = wn + j * 8 + 2 * tq;
        const float b0 = bb[cn], b1 = bb[cn + 1];
#pragma unroll
        for (int i = 0; i < 4; i++) {
            const int r0 = wm + i * 16 + qid;
            const int r1 = r0 + 8;
            float2 v0, v1;
            v0.x = acc[i][j][0] + b0; v0.y = acc[i][j][1] + b1;
            v1.x = acc[i][j][2] + b0; v1.y = acc[i][j][3] + b1;
            if (MODE == 0) {
                v0.x = to_tf32(fmaxf(v0.x, 0.f)); v0.y = to_tf32(fmaxf(v0.y, 0.f));
                v1.x = to_tf32(fmaxf(v1.x, 0.f)); v1.y = to_tf32(fmaxf(v1.y, 0.f));
            }
            if (m0 + r0 < n_e) *(float2*)(Cb + (size_t)r0 * NTOT + cn) = v0;
            if (m0 + r1 < n_e) *(float2*)(Cb + (size_t)r1 * NTOT + cn) = v1;
        }
    }
}

// ---------------- combine: out[t] = w0*y[pos0] + w1*y[pos1] ------------------
__global__ void combine_kernel(float* __restrict__ out) {
    const int i = blockIdx.x * blockDim.x + threadIdx.x;
    const int t  = i >> 7;
    const int d4 = i & 127;
    const float w0  = g_wt[2 * t];
    const float w1v = g_wt[2 * t + 1];
    const int p0 = g_pos[2 * t];
    const int p1 = g_pos[2 * t + 1];
    const float4* __restrict__ y4 = (const float4*)g_y;
    const float4 a = y4[(size_t)p0 * 128 + d4];
    const float4 b = y4[(size_t)p1 * 128 + d4];
    float4 r;
    r.x = w0 * a.x + w1v * b.x;
    r.y = w0 * a.y + w1v * b.y;
    r.z = w0 * a.z + w1v * b.z;
    r.w = w0 * a.w + w1v * b.w;
    ((float4*)out)[i] = r;
}

// ---------------- launch -----------------------------------------------------
#define SMEM_BYTES (4u * BUFF * 4u)   // 2 buffers A + 2 buffers B = 73728 B

extern "C" void kernel_launch(void* const* d_in, const int* in_sizes, int n_in,
                              void* d_out, int out_size) {
    const float* x   = (const float*)d_in[0];
    const float* rw  = (const float*)d_in[1];
    const float* rb  = (const float*)d_in[2];
    const float* w1  = (const float*)d_in[3];
    const float* b1  = (const float*)d_in[4];
    const float* w2  = (const float*)d_in[5];
    const float* b2  = (const float*)d_in[6];
    float* out = (float*)d_out;

    cudaFuncSetAttribute(moe_gemm_kernel<0>,
                         cudaFuncAttributeMaxDynamicSharedMemorySize, SMEM_BYTES);
    cudaFuncSetAttribute(moe_gemm_kernel<1>,
                         cudaFuncAttributeMaxDynamicSharedMemorySize, SMEM_BYTES);

    zero_cnt_kernel<<<1, 32>>>();
    router_kernel<<<NT / 8, 256>>>(x, rw, rb);
    pack_kernel<<<NT * 2, 128>>>(x);

    transpose_kernel<0><<<dim3(FF / 32, DD / 32, EE), dim3(32, 8)>>>(w1);
    transpose_kernel<1><<<dim3(DD / 32, FF / 32, EE), dim3(32, 8)>>>(w2);

    // GEMM1: hidden = relu(xg @ w1t^T + b1)   (K = DD, N = FF)
    moe_gemm_kernel<0><<<dim3(FF / 128, MAXTOK / 128, EE), 256, SMEM_BYTES>>>(b1);
    // GEMM2: y = hidden @ w2t^T + b2          (K = FF, N = DD)
    moe_gemm_kernel<1><<<dim3(DD / 128, MAXTOK / 128, EE), 256, SMEM_BYTES>>>(b2);

    combine_kernel<<<(NT * DD / 4) / 256, 256>>>(out);
}

// round 9
// speedup vs baseline: 5.2192x; 1.6923x over previous
#include <cuda_runtime.h>
#include <cuda_fp16.h>
#include <cstdint>
#include <math.h>

// Problem constants
#define NT      8192      // tokens = B*S
#define DD      512       // dim_model
#define FF      2048      // dim_feedforward
#define EE      8         // experts
#define MAXTOK  8192      // per-expert worst case

// ---------------- scratch (device globals; no allocations allowed) ----------
__device__ __align__(16) int    g_cnt[EE];
__device__ __align__(16) int    g_pos[NT * 2];           // e*MAXTOK+slot per (token,k)
__device__ __align__(16) float  g_wt [NT * 2];           // renormalized gate weights
__device__ __align__(16) __half g_xg[(size_t)EE * MAXTOK * DD];      // packed A rows (fp16)
__device__ __align__(16) __half g_w1t[(size_t)EE * FF * DD];         // w1^T [E][F][D] (fp16)
__device__ __align__(16) __half g_w2t[(size_t)EE * DD * FF];         // w2^T [E][D][F] (fp16)
__device__ __align__(16) __half g_hidden[(size_t)EE * MAXTOK * FF];  // hidden (fp16)
__device__ __align__(16) float  g_y[(size_t)EE * MAXTOK * DD];       // expert outputs (fp32)

// ---------------- helpers ----------------------------------------------------
__device__ __forceinline__ uint32_t smem_to_u32(const void* p) {
    uint32_t a;
    asm("{ .reg .u64 t; cvta.to.shared.u64 t, %1; cvt.u32.u64 %0, t; }"
        : "=r"(a) : "l"(p));
    return a;
}

// ---------------- counters reset --------------------------------------------
__global__ void zero_cnt_kernel() {
    if (threadIdx.x < EE) g_cnt[threadIdx.x] = 0;
}

// ---------------- router: one warp per token --------------------------------
__global__ void router_kernel(const float* __restrict__ x,
                              const float* __restrict__ rw,
                              const float* __restrict__ rb) {
    __shared__ float srw[DD * EE];
    const int tid = threadIdx.x;
    for (int i = tid; i < DD * EE; i += blockDim.x) srw[i] = rw[i];
    __syncthreads();

    const int warp = tid >> 5, lane = tid & 31;
    const int t = blockIdx.x * (blockDim.x >> 5) + warp;
    if (t >= NT) return;

    const float* __restrict__ xr = x + (size_t)t * DD;
    float acc[EE];
#pragma unroll
    for (int e = 0; e < EE; e++) acc[e] = 0.f;
    for (int d = lane; d < DD; d += 32) {
        const float xv = xr[d];
#pragma unroll
        for (int e = 0; e < EE; e++) acc[e] = fmaf(xv, srw[d * EE + e], acc[e]);
    }
#pragma unroll
    for (int e = 0; e < EE; e++)
#pragma unroll
        for (int o = 16; o > 0; o >>= 1)
            acc[e] += __shfl_xor_sync(0xffffffffu, acc[e], o);

    if (lane == 0) {
#pragma unroll
        for (int e = 0; e < EE; e++) acc[e] += rb[e];
        int e0 = 0;
#pragma unroll
        for (int e = 1; e < EE; e++) if (acc[e] > acc[e0]) e0 = e;
        int e1 = -1;
#pragma unroll
        for (int e = 0; e < EE; e++) {
            if (e == e0) continue;
            if (e1 < 0 || acc[e] > acc[e1]) e1 = e;
        }
        const float r = expf(acc[e1] - acc[e0]);
        const float w0 = 1.f / (1.f + r);
        const float w1 = r / (1.f + r);
        const int s0 = atomicAdd(&g_cnt[e0], 1);
        const int s1 = atomicAdd(&g_cnt[e1], 1);
        g_pos[2 * t]     = e0 * MAXTOK + s0;
        g_pos[2 * t + 1] = e1 * MAXTOK + s1;
        g_wt [2 * t]     = w0;
        g_wt [2 * t + 1] = w1;
    }
}

// ---------------- pack: gather token rows, convert to fp16 -------------------
__global__ void pack_kernel(const float* __restrict__ x) {
    const int row = blockIdx.x;            // 0 .. 2*NT-1
    const int t = row >> 1, k = row & 1;
    const int pos = g_pos[2 * t + k];
    const float4* __restrict__ src = (const float4*)(x + (size_t)t * DD);
    __half2* __restrict__ dst = (__half2*)(g_xg + (size_t)pos * DD);
    const float4 v = src[threadIdx.x];     // 128 threads x 4 floats
    dst[2 * threadIdx.x]     = __floats2half2_rn(v.x, v.y);
    dst[2 * threadIdx.x + 1] = __floats2half2_rn(v.z, v.w);
}

// ---------------- weight transpose (+fp16 convert) ---------------------------
// MODE 0: w1 [E][DD][FF] -> g_w1t [E][FF][DD]
// MODE 1: w2 [E][FF][DD] -> g_w2t [E][DD][FF]
template <int MODE>
__global__ void transpose_kernel(const float* __restrict__ in) {
    constexpr int R = (MODE == 0) ? DD : FF;
    constexpr int C = (MODE == 0) ? FF : DD;
    __shared__ float t[32][33];
    const int e = blockIdx.z;
    const float* __restrict__ ip = in + (size_t)e * R * C;
    __half* __restrict__ op = ((MODE == 0) ? g_w1t : g_w2t) + (size_t)e * R * C;
    const int c0 = blockIdx.x * 32, r0 = blockIdx.y * 32;
    const int tx = threadIdx.x, ty = threadIdx.y;
#pragma unroll
    for (int i = 0; i < 32; i += 8)
        t[ty + i][tx] = ip[(size_t)(r0 + ty + i) * C + c0 + tx];
    __syncthreads();
#pragma unroll
    for (int i = 0; i < 32; i += 8)
        op[(size_t)(c0 + ty + i) * R + r0 + tx] = __float2half_rn(t[tx][ty + i]);
}

// ---------------- fp16 mma.sync GEMM -----------------------------------------
// C[e][m][n] = A[e][m][:] . Bt[e][n][:]  (+bias, MODE0: relu+fp16 store)
// CTA 128x128, BK=64 halves (128B row), 256 threads = 8 warps (2m x 4n),
// warp tile 64x32, mma.sync.m16n8k16.f16, double-buffered cp.async, 2 CTA/SM.
#define BKH   64                  // K elements per tile (halves)
#define S32   36                  // smem row stride in uint32 (32 payload + 4 pad)
#define BUF32 (128 * S32)         // uint32 per (A or B) buffer

template <int MODE>
__global__ void __launch_bounds__(256, 2)
moe_gemm_kernel(const float* __restrict__ bias) {
    constexpr int K    = (MODE == 0) ? DD : FF;
    constexpr int NTOT = (MODE == 0) ? FF : DD;
    const __half* __restrict__ A  = (MODE == 0) ? g_xg  : g_hidden;
    const __half* __restrict__ Bt = (MODE == 0) ? g_w1t : g_w2t;

    const int e   = blockIdx.z;
    const int n_e = g_cnt[e];
    const int m0  = blockIdx.y * 128;
    if (m0 >= n_e) return;
    const int n0  = blockIdx.x * 128;

    extern __shared__ uint32_t sm32[];
    uint32_t* As = sm32;               // [2][BUF32]
    uint32_t* Bs = sm32 + 2 * BUF32;   // [2][BUF32]

    const int tid  = threadIdx.x;
    const int wid  = tid >> 5, lane = tid & 31;
    const int qid  = lane >> 2, tq = lane & 3;
    const int wm   = (wid >> 2) * 64;     // warp m-base
    const int wn   = (wid & 3) * 32;      // warp n-base

    const __half* __restrict__ Ab = A  + ((size_t)e * MAXTOK + m0) * K;
    const __half* __restrict__ Bb = Bt + ((size_t)e * NTOT  + n0) * K;

    const int lrow = tid >> 3;   // 0..31 (4 passes of 32 rows)
    const int lg   = tid & 7;    // 16B granule within 128B row
    const uint32_t sA = smem_to_u32(As);
    const uint32_t sB = smem_to_u32(Bs);

    float acc[4][4][4];
#pragma unroll
    for (int i = 0; i < 4; i++)
#pragma unroll
        for (int j = 0; j < 4; j++)
#pragma unroll
            for (int c = 0; c < 4; c++) acc[i][j][c] = 0.f;

    // ---- tile loader: one 128-row x 64-half tile for A and B, one commit
    auto load_tile = [&](int kt, int buf) {
        const int k0 = kt * BKH;
        const uint32_t ab = sA + (uint32_t)buf * BUF32 * 4u;
        const uint32_t bb = sB + (uint32_t)buf * BUF32 * 4u;
#pragma unroll
        for (int i = 0; i < 4; i++) {
            const int row = lrow + 32 * i;
            const uint32_t so = (uint32_t)(row * S32 + lg * 4) * 4u;
            asm volatile("cp.async.cg.shared.global [%0], [%1], 16;"
                         :: "r"(ab + so), "l"(Ab + (size_t)row * K + k0 + lg * 8) : "memory");
            asm volatile("cp.async.cg.shared.global [%0], [%1], 16;"
                         :: "r"(bb + so), "l"(Bb + (size_t)row * K + k0 + lg * 8) : "memory");
        }
        asm volatile("cp.async.commit_group;" ::: "memory");
    };

    constexpr int KT = K / BKH;
    load_tile(0, 0);

    for (int kt = 0; kt < KT; kt++) {
        if (kt + 1 < KT) {
            load_tile(kt + 1, (kt + 1) & 1);
            asm volatile("cp.async.wait_group 1;" ::: "memory");
        } else {
            asm volatile("cp.async.wait_group 0;" ::: "memory");
        }
        __syncthreads();

        const uint32_t* __restrict__ Asb = As + (kt & 1) * BUF32;
        const uint32_t* __restrict__ Bsb = Bs + (kt & 1) * BUF32;

#pragma unroll
        for (int ks = 0; ks < 4; ks++) {              // 4 x k16 per 64-half tile
            uint32_t af[4][4], bf[4][2];
            const int cb = ks * 8 + tq;               // uint32 col within row
#pragma unroll
            for (int i = 0; i < 4; i++) {
                const int r = wm + i * 16 + qid;
                af[i][0] = Asb[r * S32 + cb];
                af[i][1] = Asb[(r + 8) * S32 + cb];
                af[i][2] = Asb[r * S32 + cb + 4];
                af[i][3] = Asb[(r + 8) * S32 + cb + 4];
            }
#pragma unroll
            for (int j = 0; j < 4; j++) {
                const int n = wn + j * 8 + qid;
                bf[j][0] = Bsb[n * S32 + cb];
                bf[j][1] = Bsb[n * S32 + cb + 4];
            }
#pragma unroll
            for (int i = 0; i < 4; i++)
#pragma unroll
                for (int j = 0; j < 4; j++)
                    asm volatile(
                        "mma.sync.aligned.m16n8k16.row.col.f32.f16.f16.f32 "
                        "{%0,%1,%2,%3}, {%4,%5,%6,%7}, {%8,%9}, {%0,%1,%2,%3};"
                        : "+f"(acc[i][j][0]), "+f"(acc[i][j][1]),
                          "+f"(acc[i][j][2]), "+f"(acc[i][j][3])
                        : "r"(af[i][0]), "r"(af[i][1]), "r"(af[i][2]), "r"(af[i][3]),
                          "r"(bf[j][0]), "r"(bf[j][1]));
        }
        __syncthreads();
    }

    // ---- epilogue
    const float* __restrict__ bb = bias + (size_t)e * NTOT + n0;

    if (MODE == 0) {
        // bias + relu, store fp16 hidden
        __half* __restrict__ Cb = g_hidden + ((size_t)e * MAXTOK + m0) * NTOT + n0;
#pragma unroll
        for (int j = 0; j < 4; j++) {
            const int cn = wn + j * 8 + 2 * tq;
            const float b0 = bb[cn], b1 = bb[cn + 1];
#pragma unroll
            for (int i = 0; i < 4; i++) {
                const int r0 = wm + i * 16 + qid;
                const int r1 = r0 + 8;
                const __half2 v0 = __floats2half2_rn(fmaxf(acc[i][j][0] + b0, 0.f),
                                                     fmaxf(acc[i][j][1] + b1, 0.f));
                const __half2 v1 = __floats2half2_rn(fmaxf(acc[i][j][2] + b0, 0.f),
                                                     fmaxf(acc[i][j][3] + b1, 0.f));
                if (m0 + r0 < n_e) *(__half2*)(Cb + (size_t)r0 * NTOT + cn) = v0;
                if (m0 + r1 < n_e) *(__half2*)(Cb + (size_t)r1 * NTOT + cn) = v1;
            }
        }
    } else {
        // bias, store fp32 y
        float* __restrict__ Cb = g_y + ((size_t)e * MAXTOK + m0) * NTOT + n0;
#pragma unroll
        for (int j = 0; j < 4; j++) {
            const int cn = wn + j * 8 + 2 * tq;
            const float b0 = bb[cn], b1 = bb[cn + 1];
#pragma unroll
            for (int i = 0; i < 4; i++) {
                const int r0 = wm + i * 16 + qid;
                const int r1 = r0 + 8;
                float2 v0, v1;
                v0.x = acc[i][j][0] + b0; v0.y = acc[i][j][1] + b1;
                v1.x = acc[i][j][2] + b0; v1.y = acc[i][j][3] + b1;
                if (m0 + r0 < n_e) *(float2*)(Cb + (size_t)r0 * NTOT + cn) = v0;
                if (m0 + r1 < n_e) *(float2*)(Cb + (size_t)r1 * NTOT + cn) = v1;
            }
        }
    }
}

// ---------------- combine: out[t] = w0*y[pos0] + w1*y[pos1] ------------------
__global__ void combine_kernel(float* __restrict__ out) {
    const int i = blockIdx.x * blockDim.x + threadIdx.x;
    const int t  = i >> 7;
    const int d4 = i & 127;
    const float w0  = g_wt[2 * t];
    const float w1v = g_wt[2 * t + 1];
    const int p0 = g_pos[2 * t];
    const int p1 = g_pos[2 * t + 1];
    const float4* __restrict__ y4 = (const float4*)g_y;
    const float4 a = y4[(size_t)p0 * 128 + d4];
    const float4 b = y4[(size_t)p1 * 128 + d4];
    float4 r;
    r.x = w0 * a.x + w1v * b.x;
    r.y = w0 * a.y + w1v * b.y;
    r.z = w0 * a.z + w1v * b.z;
    r.w = w0 * a.w + w1v * b.w;
    ((float4*)out)[i] = r;
}

// ---------------- launch -----------------------------------------------------
#define SMEM_BYTES (4u * BUF32 * 4u)   // 2 buffers A + 2 buffers B = 73728 B

extern "C" void kernel_launch(void* const* d_in, const int* in_sizes, int n_in,
                              void* d_out, int out_size) {
    const float* x   = (const float*)d_in[0];
    const float* rw  = (const float*)d_in[1];
    const float* rb  = (const float*)d_in[2];
    const float* w1  = (const float*)d_in[3];
    const float* b1  = (const float*)d_in[4];
    const float* w2  = (const float*)d_in[5];
    const float* b2  = (const float*)d_in[6];
    float* out = (float*)d_out;

    cudaFuncSetAttribute(moe_gemm_kernel<0>,
                         cudaFuncAttributeMaxDynamicSharedMemorySize, SMEM_BYTES);
    cudaFuncSetAttribute(moe_gemm_kernel<1>,
                         cudaFuncAttributeMaxDynamicSharedMemorySize, SMEM_BYTES);

    zero_cnt_kernel<<<1, 32>>>();
    router_kernel<<<NT / 8, 256>>>(x, rw, rb);
    pack_kernel<<<NT * 2, 128>>>(x);

    transpose_kernel<0><<<dim3(FF / 32, DD / 32, EE), dim3(32, 8)>>>(w1);
    transpose_kernel<1><<<dim3(DD / 32, FF / 32, EE), dim3(32, 8)>>>(w2);

    // GEMM1: hidden = relu(xg @ w1t^T + b1)   (K = DD, N = FF)
    moe_gemm_kernel<0><<<dim3(FF / 128, MAXTOK / 128, EE), 256, SMEM_BYTES>>>(b1);
    // GEMM2: y = hidden @ w2t^T + b2          (K = FF, N = DD)
    moe_gemm_kernel<1><<<dim3(DD / 128, MAXTOK / 128, EE), 256, SMEM_BYTES>>>(b2);

    combine_kernel<<<(NT * DD / 4) / 256, 256>>>(out);
}

// round 10
// speedup vs baseline: 5.5645x; 1.0662x over previous
#include <cuda_runtime.h>
#include <cuda_fp16.h>
#include <cstdint>
#include <math.h>

// Problem constants
#define NT      8192      // tokens = B*S
#define DD      512       // dim_model
#define FF      2048      // dim_feedforward
#define EE      8         // experts
#define MAXTOK  8192      // per-expert worst case

// ---------------- scratch (device globals; no allocations allowed) ----------
__device__ __align__(16) int    g_cnt[EE];
__device__ __align__(16) int    g_pos[NT * 2];           // e*MAXTOK+slot per (token,k)
__device__ __align__(16) float  g_wt [NT * 2];           // renormalized gate weights
__device__ __align__(16) __half g_xg[(size_t)EE * MAXTOK * DD];      // packed A rows (fp16)
__device__ __align__(16) __half g_w1t[(size_t)EE * FF * DD];         // w1^T [E][F][D] (fp16)
__device__ __align__(16) __half g_w2t[(size_t)EE * DD * FF];         // w2^T [E][D][F] (fp16)
__device__ __align__(16) __half g_hidden[(size_t)EE * MAXTOK * FF];  // hidden (fp16)
__device__ __align__(16) float  g_y[(size_t)EE * MAXTOK * DD];       // expert outputs (fp32)

// ---------------- helpers ----------------------------------------------------
__device__ __forceinline__ uint32_t smem_to_u32(const void* p) {
    uint32_t a;
    asm("{ .reg .u64 t; cvta.to.shared.u64 t, %1; cvt.u32.u64 %0, t; }"
        : "=r"(a) : "l"(p));
    return a;
}

// ---------------- counters reset --------------------------------------------
__global__ void zero_cnt_kernel() {
    if (threadIdx.x < EE) g_cnt[threadIdx.x] = 0;
}

// ---------------- router: one warp per token --------------------------------
__global__ void router_kernel(const float* __restrict__ x,
                              const float* __restrict__ rw,
                              const float* __restrict__ rb) {
    __shared__ float srw[DD * EE];
    const int tid = threadIdx.x;
    for (int i = tid; i < DD * EE; i += blockDim.x) srw[i] = rw[i];
    __syncthreads();

    const int warp = tid >> 5, lane = tid & 31;
    const int t = blockIdx.x * (blockDim.x >> 5) + warp;
    if (t >= NT) return;

    const float* __restrict__ xr = x + (size_t)t * DD;
    float acc[EE];
#pragma unroll
    for (int e = 0; e < EE; e++) acc[e] = 0.f;
    for (int d = lane; d < DD; d += 32) {
        const float xv = xr[d];
#pragma unroll
        for (int e = 0; e < EE; e++) acc[e] = fmaf(xv, srw[d * EE + e], acc[e]);
    }
#pragma unroll
    for (int e = 0; e < EE; e++)
#pragma unroll
        for (int o = 16; o > 0; o >>= 1)
            acc[e] += __shfl_xor_sync(0xffffffffu, acc[e], o);

    if (lane == 0) {
#pragma unroll
        for (int e = 0; e < EE; e++) acc[e] += rb[e];
        int e0 = 0;
#pragma unroll
        for (int e = 1; e < EE; e++) if (acc[e] > acc[e0]) e0 = e;
        int e1 = -1;
#pragma unroll
        for (int e = 0; e < EE; e++) {
            if (e == e0) continue;
            if (e1 < 0 || acc[e] > acc[e1]) e1 = e;
        }
        const float r = expf(acc[e1] - acc[e0]);
        const float w0 = 1.f / (1.f + r);
        const float w1 = r / (1.f + r);
        const int s0 = atomicAdd(&g_cnt[e0], 1);
        const int s1 = atomicAdd(&g_cnt[e1], 1);
        g_pos[2 * t]     = e0 * MAXTOK + s0;
        g_pos[2 * t + 1] = e1 * MAXTOK + s1;
        g_wt [2 * t]     = w0;
        g_wt [2 * t + 1] = w1;
    }
}

// ---------------- pack: gather token rows, convert to fp16 -------------------
__global__ void pack_kernel(const float* __restrict__ x) {
    const int row = blockIdx.x;            // 0 .. 2*NT-1
    const int t = row >> 1, k = row & 1;
    const int pos = g_pos[2 * t + k];
    const float4* __restrict__ src = (const float4*)(x + (size_t)t * DD);
    __half2* __restrict__ dst = (__half2*)(g_xg + (size_t)pos * DD);
    const float4 v = src[threadIdx.x];     // 128 threads x 4 floats
    dst[2 * threadIdx.x]     = __floats2half2_rn(v.x, v.y);
    dst[2 * threadIdx.x + 1] = __floats2half2_rn(v.z, v.w);
}

// ---------------- weight transpose (+fp16 convert) ---------------------------
// MODE 0: w1 [E][DD][FF] -> g_w1t [E][FF][DD]
// MODE 1: w2 [E][FF][DD] -> g_w2t [E][DD][FF]
template <int MODE>
__global__ void transpose_kernel(const float* __restrict__ in) {
    constexpr int R = (MODE == 0) ? DD : FF;
    constexpr int C = (MODE == 0) ? FF : DD;
    __shared__ float t[32][33];
    const int e = blockIdx.z;
    const float* __restrict__ ip = in + (size_t)e * R * C;
    __half* __restrict__ op = ((MODE == 0) ? g_w1t : g_w2t) + (size_t)e * R * C;
    const int c0 = blockIdx.x * 32, r0 = blockIdx.y * 32;
    const int tx = threadIdx.x, ty = threadIdx.y;
#pragma unroll
    for (int i = 0; i < 32; i += 8)
        t[ty + i][tx] = ip[(size_t)(r0 + ty + i) * C + c0 + tx];
    __syncthreads();
#pragma unroll
    for (int i = 0; i < 32; i += 8)
        op[(size_t)(c0 + ty + i) * R + r0 + tx] = __float2half_rn(t[tx][ty + i]);
}

// ---------------- fp16 mma.sync GEMM (ldmatrix fragment loads) ---------------
// C[e][m][n] = A[e][m][:] . Bt[e][n][:]  (+bias, MODE0: relu+fp16 store)
// CTA 128x128, BK=64 halves (128B row), 256 threads = 8 warps (2m x 4n),
// warp tile 64x32, mma.sync.m16n8k16.f16, ldmatrix.x4, 2 CTA/SM.
#define BKH   64                  // K elements per tile (halves)
#define S32   36                  // smem row stride in uint32 (32 payload + 4 pad)
#define BUF32 (128 * S32)         // uint32 per (A or B) buffer

template <int MODE>
__global__ void __launch_bounds__(256, 2)
moe_gemm_kernel(const float* __restrict__ bias) {
    constexpr int K    = (MODE == 0) ? DD : FF;
    constexpr int NTOT = (MODE == 0) ? FF : DD;
    const __half* __restrict__ A  = (MODE == 0) ? g_xg  : g_hidden;
    const __half* __restrict__ Bt = (MODE == 0) ? g_w1t : g_w2t;

    const int e   = blockIdx.z;
    const int n_e = g_cnt[e];
    const int m0  = blockIdx.y * 128;
    if (m0 >= n_e) return;
    const int n0  = blockIdx.x * 128;

    extern __shared__ uint32_t sm32[];
    uint32_t* As = sm32;               // [2][BUF32]
    uint32_t* Bs = sm32 + 2 * BUF32;   // [2][BUF32]

    const int tid  = threadIdx.x;
    const int wid  = tid >> 5, lane = tid & 31;
    const int qid  = lane >> 2, tq = lane & 3;
    const int wm   = (wid >> 2) * 64;     // warp m-base
    const int wn   = (wid & 3) * 32;      // warp n-base

    const __half* __restrict__ Ab = A  + ((size_t)e * MAXTOK + m0) * K;
    const __half* __restrict__ Bb = Bt + ((size_t)e * NTOT  + n0) * K;

    const int lrow = tid >> 3;   // 0..31 (4 passes of 32 rows)
    const int lg   = tid & 7;    // 16B granule within 128B row
    const uint32_t sA = smem_to_u32(As);
    const uint32_t sB = smem_to_u32(Bs);

    // ---- ldmatrix per-lane offsets (bytes within a buffer)
    // A frag i: groups 0..3 -> (rows+0,kLo) (rows+8,kLo) (rows+0,kHi) (rows+8,kHi)
    // B pair jp: groups 0..3 -> (n+0,kLo) (n+0,kHi) (n+8,kLo) (n+8,kHi)
    const int grp = lane >> 3, lr = lane & 7;
    uint32_t aOff[4], bOff[2];
#pragma unroll
    for (int i = 0; i < 4; i++) {
        const int row = wm + i * 16 + lr + ((grp & 1) ? 8 : 0);
        const int col = (grp & 2) ? 4 : 0;
        aOff[i] = (uint32_t)(row * S32 + col) * 4u;
    }
#pragma unroll
    for (int jp = 0; jp < 2; jp++) {
        const int row = wn + jp * 16 + lr + ((grp & 2) ? 8 : 0);
        const int col = (grp & 1) ? 4 : 0;
        bOff[jp] = (uint32_t)(row * S32 + col) * 4u;
    }

    float acc[4][4][4];
#pragma unroll
    for (int i = 0; i < 4; i++)
#pragma unroll
        for (int j = 0; j < 4; j++)
#pragma unroll
            for (int c = 0; c < 4; c++) acc[i][j][c] = 0.f;

    // ---- tile loader: one 128-row x 64-half tile for A and B, one commit
    auto load_tile = [&](int kt, int buf) {
        const int k0 = kt * BKH;
        const uint32_t ab = sA + (uint32_t)buf * BUF32 * 4u;
        const uint32_t bb = sB + (uint32_t)buf * BUF32 * 4u;
#pragma unroll
        for (int i = 0; i < 4; i++) {
            const int row = lrow + 32 * i;
            const uint32_t so = (uint32_t)(row * S32 + lg * 4) * 4u;
            asm volatile("cp.async.cg.shared.global [%0], [%1], 16;"
                         :: "r"(ab + so), "l"(Ab + (size_t)row * K + k0 + lg * 8) : "memory");
            asm volatile("cp.async.cg.shared.global [%0], [%1], 16;"
                         :: "r"(bb + so), "l"(Bb + (size_t)row * K + k0 + lg * 8) : "memory");
        }
        asm volatile("cp.async.commit_group;" ::: "memory");
    };

    constexpr int KT = K / BKH;
    load_tile(0, 0);

    for (int kt = 0; kt < KT; kt++) {
        if (kt + 1 < KT) {
            load_tile(kt + 1, (kt + 1) & 1);
            asm volatile("cp.async.wait_group 1;" ::: "memory");
        } else {
            asm volatile("cp.async.wait_group 0;" ::: "memory");
        }
        __syncthreads();

        const uint32_t aBase = sA + (uint32_t)(kt & 1) * BUF32 * 4u;
        const uint32_t bBase = sB + (uint32_t)(kt & 1) * BUF32 * 4u;

#pragma unroll
        for (int ks = 0; ks < 4; ks++) {              // 4 x k16 per 64-half tile
            const uint32_t kadd = (uint32_t)ks * 32u; // 8 uint32 = 32 bytes
            uint32_t af[4][4], bf[4][2];
#pragma unroll
            for (int i = 0; i < 4; i++)
                asm volatile(
                    "ldmatrix.sync.aligned.m8n8.x4.shared.b16 {%0,%1,%2,%3}, [%4];"
                    : "=r"(af[i][0]), "=r"(af[i][1]), "=r"(af[i][2]), "=r"(af[i][3])
                    : "r"(aBase + aOff[i] + kadd));
#pragma unroll
            for (int jp = 0; jp < 2; jp++)
                asm volatile(
                    "ldmatrix.sync.aligned.m8n8.x4.shared.b16 {%0,%1,%2,%3}, [%4];"
                    : "=r"(bf[2 * jp][0]), "=r"(bf[2 * jp][1]),
                      "=r"(bf[2 * jp + 1][0]), "=r"(bf[2 * jp + 1][1])
                    : "r"(bBase + bOff[jp] + kadd));
#pragma unroll
            for (int i = 0; i < 4; i++)
#pragma unroll
                for (int j = 0; j < 4; j++)
                    asm volatile(
                        "mma.sync.aligned.m16n8k16.row.col.f32.f16.f16.f32 "
                        "{%0,%1,%2,%3}, {%4,%5,%6,%7}, {%8,%9}, {%0,%1,%2,%3};"
                        : "+f"(acc[i][j][0]), "+f"(acc[i][j][1]),
                          "+f"(acc[i][j][2]), "+f"(acc[i][j][3])
                        : "r"(af[i][0]), "r"(af[i][1]), "r"(af[i][2]), "r"(af[i][3]),
                          "r"(bf[j][0]), "r"(bf[j][1]));
        }
        __syncthreads();
    }

    // ---- epilogue
    const float* __restrict__ bb = bias + (size_t)e * NTOT + n0;

    if (MODE == 0) {
        // bias + relu, store fp16 hidden
        __half* __restrict__ Cb = g_hidden + ((size_t)e * MAXTOK + m0) * NTOT + n0;
#pragma unroll
        for (int j = 0; j < 4; j++) {
            const int cn = wn + j * 8 + 2 * tq;
            const float b0 = bb[cn], b1 = bb[cn + 1];
#pragma unroll
            for (int i = 0; i < 4; i++) {
                const int r0 = wm + i * 16 + qid;
                const int r1 = r0 + 8;
                const __half2 v0 = __floats2half2_rn(fmaxf(acc[i][j][0] + b0, 0.f),
                                                     fmaxf(acc[i][j][1] + b1, 0.f));
                const __half2 v1 = __floats2half2_rn(fmaxf(acc[i][j][2] + b0, 0.f),
                                                     fmaxf(acc[i][j][3] + b1, 0.f));
                if (m0 + r0 < n_e) *(__half2*)(Cb + (size_t)r0 * NTOT + cn) = v0;
                if (m0 + r1 < n_e) *(__half2*)(Cb + (size_t)r1 * NTOT + cn) = v1;
            }
        }
    } else {
        // bias, store fp32 y
        float* __restrict__ Cb = g_y + ((size_t)e * MAXTOK + m0) * NTOT + n0;
#pragma unroll
        for (int j = 0; j < 4; j++) {
            const int cn = wn + j * 8 + 2 * tq;
            const float b0 = bb[cn], b1 = bb[cn + 1];
#pragma unroll
            for (int i = 0; i < 4; i++) {
                const int r0 = wm + i * 16 + qid;
                const int r1 = r0 + 8;
                float2 v0, v1;
                v0.x = acc[i][j][0] + b0; v0.y = acc[i][j][1] + b1;
                v1.x = acc[i][j][2] + b0; v1.y = acc[i][j][3] + b1;
                if (m0 + r0 < n_e) *(float2*)(Cb + (size_t)r0 * NTOT + cn) = v0;
                if (m0 + r1 < n_e) *(float2*)(Cb + (size_t)r1 * NTOT + cn) = v1;
            }
        }
    }
}

// ---------------- combine: out[t] = w0*y[pos0] + w1*y[pos1] ------------------
__global__ void combine_kernel(float* __restrict__ out) {
    const int i = blockIdx.x * blockDim.x + threadIdx.x;
    const int t  = i >> 7;
    const int d4 = i & 127;
    const float w0  = g_wt[2 * t];
    const float w1v = g_wt[2 * t + 1];
    const int p0 = g_pos[2 * t];
    const int p1 = g_pos[2 * t + 1];
    const float4* __restrict__ y4 = (const float4*)g_y;
    const float4 a = y4[(size_t)p0 * 128 + d4];
    const float4 b = y4[(size_t)p1 * 128 + d4];
    float4 r;
    r.x = w0 * a.x + w1v * b.x;
    r.y = w0 * a.y + w1v * b.y;
    r.z = w0 * a.z + w1v * b.z;
    r.w = w0 * a.w + w1v * b.w;
    ((float4*)out)[i] = r;
}

// ---------------- launch -----------------------------------------------------
#define SMEM_BYTES (4u * BUF32 * 4u)   // 2 buffers A + 2 buffers B = 73728 B

extern "C" void kernel_launch(void* const* d_in, const int* in_sizes, int n_in,
                              void* d_out, int out_size) {
    const float* x   = (const float*)d_in[0];
    const float* rw  = (const float*)d_in[1];
    const float* rb  = (const float*)d_in[2];
    const float* w1  = (const float*)d_in[3];
    const float* b1  = (const float*)d_in[4];
    const float* w2  = (const float*)d_in[5];
    const float* b2  = (const float*)d_in[6];
    float* out = (float*)d_out;

    cudaFuncSetAttribute(moe_gemm_kernel<0>,
                         cudaFuncAttributeMaxDynamicSharedMemorySize, SMEM_BYTES);
    cudaFuncSetAttribute(moe_gemm_kernel<1>,
                         cudaFuncAttributeMaxDynamicSharedMemorySize, SMEM_BYTES);

    zero_cnt_kernel<<<1, 32>>>();
    router_kernel<<<NT / 8, 256>>>(x, rw, rb);
    pack_kernel<<<NT * 2, 128>>>(x);

    transpose_kernel<0><<<dim3(FF / 32, DD / 32, EE), dim3(32, 8)>>>(w1);
    transpose_kernel<1><<<dim3(DD / 32, FF / 32, EE), dim3(32, 8)>>>(w2);

    // GEMM1: hidden = relu(xg @ w1t^T + b1)   (K = DD, N = FF)
    moe_gemm_kernel<0><<<dim3(FF / 128, MAXTOK / 128, EE), 256, SMEM_BYTES>>>(b1);
    // GEMM2: y = hidden @ w2t^T + b2          (K = FF, N = DD)
    moe_gemm_kernel<1><<<dim3(DD / 128, MAXTOK / 128, EE), 256, SMEM_BYTES>>>(b2);

    combine_kernel<<<(NT * DD / 4) / 256, 256>>>(out);
}